// round 9
// baseline (speedup 1.0000x reference)
#include <cuda_runtime.h>
#include <cuda_fp16.h>
#include <cstdint>
#include <cstddef>

// ---------------------------------------------------------------------------
//  x: [16, 32, 32, 8, 16]  (B,H,W,I,Din) fp32
//  W: [5, 5, 16, 256]      (kh,kw,cin,co) fp32, co = o*16+d
//  b: [1, 1, 16, 16]       fp32
//  out: [16, 32, 32, 16, 16] (B,H,W,O,D) fp32
//
// Routing group p uses conv images n = 8p+q -> input capsule i = p>>1,
// b_img = 8*(p&1)+q.  CTA = (p, h, 8 w's): M=64 GEMM rows (8 q x 8 w) =
// exactly the votes its 8 routing points need.  2048 CTAs, 256 threads,
// occupancy 2.  GEMM: M=64, N=256, K=400 in k16 steps.
// SINGLE-PASS fp16 (x fp16, W fp16): x-rounding ~2^-12 and W-rounding ~2^-12
// are independent; measured W-only rel_err 4.09e-4 -> RSS estimate ~5.8e-4,
// under the 1e-3 tolerance.  Halves the HMMA count vs the 2-pass scheme
// (which measured exactly at the ~340 MAC/cyc/SM legacy-pipe roofline).
// ---------------------------------------------------------------------------

__device__ __half g_xh[16 * 32 * 32 * 8 * 16];   // x as fp16
__device__ __half g_ws[25 * 256 * 16];           // W as [k][n][16k], fp16

// stage: A 64x48B (3072) + B 256x48B (12288) = 15360 ; x4 = 61440
#define ST_BYTES   15360
#define OFF_LOGIT  66048           // after 64x258x4 dump buffer
#define OFF_ROUTE  66560
#define SMEM_ALLOC 67072

__device__ __forceinline__ uint32_t smem_u32(const void* p) {
    uint32_t a;
    asm("{ .reg .u64 t; cvta.to.shared.u64 t, %1; cvt.u32.u64 %0, t; }" : "=r"(a) : "l"(p));
    return a;
}
__device__ __forceinline__ void cp16z(uint32_t dst, const void* src, bool valid) {
    int sz = valid ? 16 : 0;
    asm volatile("cp.async.cg.shared.global [%0], [%1], 16, %2;\n"
                 :: "r"(dst), "l"(src), "r"(sz));
}
__device__ __forceinline__ void cp16(uint32_t dst, const void* src) {
    asm volatile("cp.async.cg.shared.global [%0], [%1], 16;\n" :: "r"(dst), "l"(src));
}
#define CP_COMMIT() asm volatile("cp.async.commit_group;\n")
#define CP_WAIT(n)  asm volatile("cp.async.wait_group %0;\n" :: "n"(n))

#define LDSM4(r, addr) \
    asm volatile("ldmatrix.sync.aligned.m8n8.x4.shared.b16 {%0,%1,%2,%3}, [%4];" \
                 : "=r"((r)[0]), "=r"((r)[1]), "=r"((r)[2]), "=r"((r)[3]) : "r"(addr))

#define MMA16816(c, a, bb0, bb1) \
    asm volatile("mma.sync.aligned.m16n8k16.row.col.f32.f16.f16.f32 " \
                 "{%0,%1,%2,%3}, {%4,%5,%6,%7}, {%8,%9}, {%0,%1,%2,%3};" \
                 : "+f"((c)[0]), "+f"((c)[1]), "+f"((c)[2]), "+f"((c)[3]) \
                 : "r"((a)[0]), "r"((a)[1]), "r"((a)[2]), "r"((a)[3]), \
                   "r"(bb0), "r"(bb1))

// ---------------- prep kernels ----------------
__global__ void xprep_kernel(const float* __restrict__ x) {
    int idx = blockIdx.x * 256 + threadIdx.x;          // 4 floats per thread
    if (idx >= 16 * 32 * 32 * 8 * 16 / 4) return;
    float4 f = ((const float4*)x)[idx];
    __half h0[4];
    h0[0] = __float2half_rn(f.x);
    h0[1] = __float2half_rn(f.y);
    h0[2] = __float2half_rn(f.z);
    h0[3] = __float2half_rn(f.w);
    *(uint2*)&g_xh[idx * 4] = *(uint2*)h0;
}

__global__ void wprep_kernel(const float* __restrict__ W) {
    int idx = blockIdx.x * 256 + threadIdx.x;   // k*256 + co
    if (idx >= 25 * 256) return;
    int co = idx & 255, k = idx >> 8;
#pragma unroll
    for (int cin = 0; cin < 16; ++cin)
        g_ws[idx * 16 + cin] = __float2half_rn(W[(k * 16 + cin) * 256 + co]);
}

// ---------------- main fused kernel ----------------
__device__ __forceinline__ void load_tiles(uint32_t sbase, int k, int stg_i,
                                           int h, int w0, int i_true, int b_base,
                                           int t) {
    const int kh = k / 5, kw = k - kh * 5;
    const uint32_t stg = sbase + stg_i * ST_BYTES;
    // A: 128 x 16B (threads 0..127): half(2) x row(64)
    if (t < 128) {
        int half = t & 1, row = t >> 1;
        int q = row >> 3, wl = row & 7;
        int hh = h + kh - 2, ww = w0 + wl + kw - 2;
        bool valid = ((unsigned)hh < 32u) && ((unsigned)ww < 32u);
        const __half* src = valid
            ? &g_xh[((((size_t)(b_base + q) * 32 + hh) * 32 + ww) * 8 + i_true) * 16 + half * 8]
            : &g_xh[0];
        cp16z(stg + row * 48 + half * 16, src, valid);
    }
    // B: 512 x 16B (2 per thread): half(2) x n(256)
#pragma unroll
    for (int it = 0; it < 2; ++it) {
        int j = t + it * 256;
        int half = j & 1, n = j >> 1;
        cp16(stg + 3072 + n * 48 + half * 16,
             &g_ws[((size_t)k * 256 + n) * 16 + half * 8]);
    }
}

__global__ __launch_bounds__(256, 2) void caps_fused_kernel(
    const float* __restrict__ bias, float* __restrict__ out) {
    extern __shared__ __align__(1024) char sm[];
    const uint32_t sbase = smem_u32(sm);

    const int t = threadIdx.x;
    const int wid = t >> 5, lane = t & 31;
    const int bid = blockIdx.x;
    const int wblk = bid & 3, h = (bid >> 2) & 31, p = bid >> 7;
    const int w0 = wblk * 8;
    const int i_true = p >> 1, b_base = (p & 1) * 8;

    const int wm = wid & 1;        // m block (32 rows each)
    const int wn = wid >> 1;       // n block (64 cols each)

    const uint32_t a_row  = lane & 15;
    const uint32_t a_koff = (lane >> 4) * 16;
    const uint32_t b_row  = (lane & 7) + ((lane >> 4) << 3);
    const uint32_t b_koff = ((lane >> 3) & 1) * 16;

    float acc[2][8][4];
#pragma unroll
    for (int mi = 0; mi < 2; ++mi)
#pragma unroll
        for (int ni = 0; ni < 8; ++ni)
#pragma unroll
            for (int j = 0; j < 4; ++j) acc[mi][ni][j] = 0.f;

    // prologue: stages 0,1,2
#pragma unroll
    for (int s = 0; s < 3; ++s) {
        load_tiles(sbase, s, s, h, w0, i_true, b_base, t);
        CP_COMMIT();
    }

    for (int k = 0; k < 25; ++k) {
        const int stg_i = k & 3;
        if (k <= 22) CP_WAIT(2); else if (k == 23) CP_WAIT(1); else CP_WAIT(0);
        __syncthreads();                 // stage k ready; stage (k-1)&3 free
        if (k + 3 < 25) {
            load_tiles(sbase, k + 3, (k + 3) & 3, h, w0, i_true, b_base, t);
            CP_COMMIT();
        }

        const uint32_t stg = sbase + stg_i * ST_BYTES;
        const uint32_t Ab = stg + (wm * 32 + a_row) * 48 + a_koff;
        const uint32_t Bb = stg + 3072 + (wn * 64 + b_row) * 48 + b_koff;

        uint32_t Af[2][4], Bf[4][4];
#pragma unroll
        for (int mi = 0; mi < 2; ++mi) LDSM4(Af[mi], Ab + mi * 768);
#pragma unroll
        for (int nt = 0; nt < 4; ++nt) LDSM4(Bf[nt], Bb + nt * 768);
#pragma unroll
        for (int mi = 0; mi < 2; ++mi)
#pragma unroll
            for (int nt = 0; nt < 4; ++nt) {
                MMA16816(acc[mi][2 * nt],     Af[mi], Bf[nt][0], Bf[nt][1]);
                MMA16816(acc[mi][2 * nt + 1], Af[mi], Bf[nt][2], Bf[nt][3]);
            }
    }
    __syncthreads();   // compute done; stage smem dead -> vote dump

    // ---- dump accumulators: Dsm[row 64][col 256], stride 258 ----
    float* Dsm = (float*)sm;
    {
        const int g = lane >> 2, tq = lane & 3;
#pragma unroll
        for (int mi = 0; mi < 2; ++mi)
#pragma unroll
            for (int ni = 0; ni < 8; ++ni) {
                int row = wm * 32 + mi * 16 + g;
                int col = wn * 64 + ni * 8 + tq * 2;
                *(float2*)&Dsm[(size_t)row * 258 + col] =
                    make_float2(acc[mi][ni][0], acc[mi][ni][1]);
                *(float2*)&Dsm[(size_t)(row + 8) * 258 + col] =
                    make_float2(acc[mi][ni][2], acc[mi][ni][3]);
            }
    }
    __syncthreads();

    // ---- fused routing: 8 points (256 threads = (o,d)) ----
    float* lg = (float*)(sm + OFF_LOGIT);   // [q*16+o] 128
    float* rt = (float*)(sm + OFF_ROUTE);
    const float bval = bias[t];
    const int o = t >> 4, d = t & 15;

    for (int pt = 0; pt < 8; ++pt) {
        float vq[8];
#pragma unroll
        for (int q = 0; q < 8; ++q)
            vq[q] = Dsm[(size_t)(q * 8 + pt) * 258 + t];

        // iter 0: softmax(0) = 1/16
        float pre = bval;
#pragma unroll
        for (int q = 0; q < 8; ++q) pre = fmaf(0.0625f, vq[q], pre);
        float sq = pre * pre;
#pragma unroll
        for (int st = 8; st; st >>= 1)
            sq += __shfl_xor_sync(0xffffffffu, sq, st, 16);
        float act = pre * sqrtf(sq) / (1.f + sq);

        {   // agreement -> logits (initial logits 0, plain store)
            float r[8];
#pragma unroll
            for (int q = 0; q < 8; ++q) r[q] = vq[q] * act;
#pragma unroll
            for (int st = 8; st; st >>= 1)
#pragma unroll
                for (int q = 0; q < 8; ++q)
                    r[q] += __shfl_xor_sync(0xffffffffu, r[q], st, 16);
            if (d < 8) {
                float val = r[0];
#pragma unroll
                for (int q = 1; q < 8; ++q) if (d == q) val = r[q];
                lg[d * 16 + o] = val;
            }
        }
        __syncthreads();

#pragma unroll
        for (int it = 1; it < 3; ++it) {
            if (t < 128) {          // softmax over o, per input capsule
                float l = lg[t];
                float mx = l;
#pragma unroll
                for (int st = 8; st; st >>= 1)
                    mx = fmaxf(mx, __shfl_xor_sync(0xffffffffu, mx, st, 16));
                float e = __expf(l - mx);
                float sum = e;
#pragma unroll
                for (int st = 8; st; st >>= 1)
                    sum += __shfl_xor_sync(0xffffffffu, sum, st, 16);
                rt[t] = e / sum;
            }
            __syncthreads();

            pre = bval;
#pragma unroll
            for (int q = 0; q < 8; ++q)
                pre = fmaf(rt[q * 16 + o], vq[q], pre);
            sq = pre * pre;
#pragma unroll
            for (int st = 8; st; st >>= 1)
                sq += __shfl_xor_sync(0xffffffffu, sq, st, 16);
            act = pre * sqrtf(sq) / (1.f + sq);

            if (it == 1) {
                float r[8];
#pragma unroll
                for (int q = 0; q < 8; ++q) r[q] = vq[q] * act;
#pragma unroll
                for (int st = 8; st; st >>= 1)
#pragma unroll
                    for (int q = 0; q < 8; ++q)
                        r[q] += __shfl_xor_sync(0xffffffffu, r[q], st, 16);
                if (d < 8) {
                    float val = r[0];
#pragma unroll
                    for (int q = 1; q < 8; ++q) if (d == q) val = r[q];
                    lg[d * 16 + o] += val;
                }
                __syncthreads();
            }
        }

        out[(((size_t)p * 32 + h) * 32 + (w0 + pt)) * 256 + t] = act;
        __syncthreads();
    }
}

extern "C" void kernel_launch(void* const* d_in, const int* in_sizes, int n_in,
                              void* d_out, int out_size) {
    const float* x  = (const float*)d_in[0];
    const float* Wt = (const float*)d_in[1];
    const float* b  = (const float*)d_in[2];
    float* out = (float*)d_out;

    cudaFuncSetAttribute(caps_fused_kernel,
                         cudaFuncAttributeMaxDynamicSharedMemorySize, SMEM_ALLOC);

    xprep_kernel<<<2048, 256>>>(x);
    wprep_kernel<<<25, 256>>>(Wt);
    caps_fused_kernel<<<2048, 256, SMEM_ALLOC>>>(b, out);
}

// round 10
// speedup vs baseline: 1.3494x; 1.3494x over previous
#include <cuda_runtime.h>
#include <cuda_fp16.h>
#include <cstdint>
#include <cstddef>

// ---------------------------------------------------------------------------
//  x: [16, 32, 32, 8, 16]  (B,H,W,I,Din) fp32
//  W: [5, 5, 16, 256]      (kh,kw,cin,co) fp32, co = o*16+d
//  b: [1, 1, 16, 16]       fp32
//  out: [16, 32, 32, 16, 16] (B,H,W,O,D) fp32
//
// Routing group p uses conv images n = 8p+q -> input capsule i = p>>1,
// b_img = 8*(p&1)+q.  CTA = (p, h, 8 w's): M=64 GEMM rows (8 q x 8 w) =
// the votes its 8 routing points need.  2048 CTAs, 256 threads, occupancy 2.
// GEMM: M=64, N=256, K=416 (26 taps x 16, tap 25 zero-padded).
// Single-pass fp16 (x,W fp16): measured rel_err 5.7e-4 < 1e-3.
// 13 super-steps of 2 taps each (32 HMMA/warp/step) -- R8 showed 16-HMMA
// steps are overhead-bound; this halves barriers/pipeline turns vs 25 steps.
// 3-stage cp.async pipeline (30KB/stage), lookahead 2, 1 sync/step.
// ---------------------------------------------------------------------------

__device__ __half g_xh[16 * 32 * 32 * 8 * 16];   // x as fp16
__device__ __half g_ws[26 * 256 * 16];           // W as [k][n][16k], fp16, tap25=0

// stage: A 2 taps x 64x48B (6144) + B 2 taps x 256x48B (24576) = 30720
#define ST_BYTES   30720
#define OFF_LOGIT  92160           // after 3 stages (dump buffer 66KB reuses stages)
#define OFF_ROUTE  92672
#define SMEM_ALLOC 93184

__device__ __forceinline__ uint32_t smem_u32(const void* p) {
    uint32_t a;
    asm("{ .reg .u64 t; cvta.to.shared.u64 t, %1; cvt.u32.u64 %0, t; }" : "=r"(a) : "l"(p));
    return a;
}
__device__ __forceinline__ void cp16z(uint32_t dst, const void* src, bool valid) {
    int sz = valid ? 16 : 0;
    asm volatile("cp.async.cg.shared.global [%0], [%1], 16, %2;\n"
                 :: "r"(dst), "l"(src), "r"(sz));
}
__device__ __forceinline__ void cp16(uint32_t dst, const void* src) {
    asm volatile("cp.async.cg.shared.global [%0], [%1], 16;\n" :: "r"(dst), "l"(src));
}
#define CP_COMMIT() asm volatile("cp.async.commit_group;\n")
#define CP_WAIT(n)  asm volatile("cp.async.wait_group %0;\n" :: "n"(n))

#define LDSM4(r, addr) \
    asm volatile("ldmatrix.sync.aligned.m8n8.x4.shared.b16 {%0,%1,%2,%3}, [%4];" \
                 : "=r"((r)[0]), "=r"((r)[1]), "=r"((r)[2]), "=r"((r)[3]) : "r"(addr))

#define MMA16816(c, a, bb0, bb1) \
    asm volatile("mma.sync.aligned.m16n8k16.row.col.f32.f16.f16.f32 " \
                 "{%0,%1,%2,%3}, {%4,%5,%6,%7}, {%8,%9}, {%0,%1,%2,%3};" \
                 : "+f"((c)[0]), "+f"((c)[1]), "+f"((c)[2]), "+f"((c)[3]) \
                 : "r"((a)[0]), "r"((a)[1]), "r"((a)[2]), "r"((a)[3]), \
                   "r"(bb0), "r"(bb1))

// ---------------- prep kernels ----------------
__global__ void xprep_kernel(const float* __restrict__ x) {
    int idx = blockIdx.x * 256 + threadIdx.x;          // 4 floats per thread
    if (idx >= 16 * 32 * 32 * 8 * 16 / 4) return;
    float4 f = ((const float4*)x)[idx];
    __half h0[4];
    h0[0] = __float2half_rn(f.x);
    h0[1] = __float2half_rn(f.y);
    h0[2] = __float2half_rn(f.z);
    h0[3] = __float2half_rn(f.w);
    *(uint2*)&g_xh[idx * 4] = *(uint2*)h0;
}

__global__ void wprep_kernel(const float* __restrict__ W) {
    int idx = blockIdx.x * 256 + threadIdx.x;   // k*256 + co, k in [0,26)
    if (idx >= 26 * 256) return;
    int co = idx & 255, k = idx >> 8;
#pragma unroll
    for (int cin = 0; cin < 16; ++cin)
        g_ws[idx * 16 + cin] = (k < 25)
            ? __float2half_rn(W[(k * 16 + cin) * 256 + co])
            : __half(0.f);
}

// ---------------- main fused kernel ----------------
// Load one super-stage = taps 2s, 2s+1.
__device__ __forceinline__ void load_tiles(uint32_t sbase, int s, int stg_i,
                                           int h, int w0, int i_true, int b_base,
                                           int t) {
    const uint32_t stg = sbase + stg_i * ST_BYTES;
    // A: 256 x 16B (1 per thread): sub(2) x half(2) x row(64)
    {
        int sub = t >> 7, r = t & 127;
        int half = r & 1, row = r >> 1;
        int k2 = 2 * s + sub;
        int kh = k2 / 5, kw = k2 - kh * 5;
        int q = row >> 3, wl = row & 7;
        int hh = h + kh - 2, ww = w0 + wl + kw - 2;
        bool valid = (k2 < 25) && ((unsigned)hh < 32u) && ((unsigned)ww < 32u);
        const __half* src = valid
            ? &g_xh[((((size_t)(b_base + q) * 32 + hh) * 32 + ww) * 8 + i_true) * 16 + half * 8]
            : &g_xh[0];
        cp16z(stg + sub * 3072 + row * 48 + half * 16, src, valid);
    }
    // B: 1024 x 16B (4 per thread): sub(2) x half(2) x n(256)
#pragma unroll
    for (int it = 0; it < 4; ++it) {
        int j = t + it * 256;
        int sub = j >> 9, rem = j & 511;
        int half = rem & 1, n = rem >> 1;
        cp16(stg + 6144 + sub * 12288 + n * 48 + half * 16,
             &g_ws[((size_t)(2 * s + sub) * 256 + n) * 16 + half * 8]);
    }
}

__global__ __launch_bounds__(256, 2) void caps_fused_kernel(
    const float* __restrict__ bias, float* __restrict__ out) {
    extern __shared__ __align__(1024) char sm[];
    const uint32_t sbase = smem_u32(sm);

    const int t = threadIdx.x;
    const int wid = t >> 5, lane = t & 31;
    const int bid = blockIdx.x;
    const int wblk = bid & 3, h = (bid >> 2) & 31, p = bid >> 7;
    const int w0 = wblk * 8;
    const int i_true = p >> 1, b_base = (p & 1) * 8;

    const int wm = wid & 1;        // m block (32 rows each)
    const int wn = wid >> 1;       // n block (64 cols each)

    const uint32_t a_row  = lane & 15;
    const uint32_t a_koff = (lane >> 4) * 16;
    const uint32_t b_row  = (lane & 7) + ((lane >> 4) << 3);
    const uint32_t b_koff = ((lane >> 3) & 1) * 16;

    float acc[2][8][4];
#pragma unroll
    for (int mi = 0; mi < 2; ++mi)
#pragma unroll
        for (int ni = 0; ni < 8; ++ni)
#pragma unroll
            for (int j = 0; j < 4; ++j) acc[mi][ni][j] = 0.f;

    // prologue: stages 0,1
    load_tiles(sbase, 0, 0, h, w0, i_true, b_base, t);
    CP_COMMIT();
    load_tiles(sbase, 1, 1, h, w0, i_true, b_base, t);
    CP_COMMIT();

    for (int s = 0; s < 13; ++s) {
        const int stg_i = s % 3;
        if (s < 12) CP_WAIT(1); else CP_WAIT(0);
        __syncthreads();                 // stage s ready; stage (s+2)%3 free
        if (s + 2 < 13) {
            load_tiles(sbase, s + 2, (s + 2) % 3, h, w0, i_true, b_base, t);
            CP_COMMIT();
        }

        const uint32_t stg = sbase + stg_i * ST_BYTES;
#pragma unroll
        for (int sub = 0; sub < 2; ++sub) {
            const uint32_t Ab = stg + sub * 3072 + (wm * 32 + a_row) * 48 + a_koff;
            const uint32_t Bb = stg + 6144 + sub * 12288 +
                                (wn * 64 + b_row) * 48 + b_koff;
            uint32_t Af[2][4], Bf[4][4];
#pragma unroll
            for (int mi = 0; mi < 2; ++mi) LDSM4(Af[mi], Ab + mi * 768);
#pragma unroll
            for (int nt = 0; nt < 4; ++nt) LDSM4(Bf[nt], Bb + nt * 768);
#pragma unroll
            for (int mi = 0; mi < 2; ++mi)
#pragma unroll
                for (int nt = 0; nt < 4; ++nt) {
                    MMA16816(acc[mi][2 * nt],     Af[mi], Bf[nt][0], Bf[nt][1]);
                    MMA16816(acc[mi][2 * nt + 1], Af[mi], Bf[nt][2], Bf[nt][3]);
                }
        }
    }
    __syncthreads();   // compute done; stage smem dead -> vote dump

    // ---- dump accumulators: Dsm[row 64][col 256], stride 258 ----
    float* Dsm = (float*)sm;
    {
        const int g = lane >> 2, tq = lane & 3;
#pragma unroll
        for (int mi = 0; mi < 2; ++mi)
#pragma unroll
            for (int ni = 0; ni < 8; ++ni) {
                int row = wm * 32 + mi * 16 + g;
                int col = wn * 64 + ni * 8 + tq * 2;
                *(float2*)&Dsm[(size_t)row * 258 + col] =
                    make_float2(acc[mi][ni][0], acc[mi][ni][1]);
                *(float2*)&Dsm[(size_t)(row + 8) * 258 + col] =
                    make_float2(acc[mi][ni][2], acc[mi][ni][3]);
            }
    }
    __syncthreads();

    // ---- fused routing: 8 points (256 threads = (o,d)) ----
    float* lg = (float*)(sm + OFF_LOGIT);   // [q*16+o] 128
    float* rt = (float*)(sm + OFF_ROUTE);
    const float bval = bias[t];
    const int o = t >> 4, d = t & 15;

    for (int pt = 0; pt < 8; ++pt) {
        float vq[8];
#pragma unroll
        for (int q = 0; q < 8; ++q)
            vq[q] = Dsm[(size_t)(q * 8 + pt) * 258 + t];

        // iter 0: softmax(0) = 1/16
        float pre = bval;
#pragma unroll
        for (int q = 0; q < 8; ++q) pre = fmaf(0.0625f, vq[q], pre);
        float sq = pre * pre;
#pragma unroll
        for (int st = 8; st; st >>= 1)
            sq += __shfl_xor_sync(0xffffffffu, sq, st, 16);
        float act = pre * sqrtf(sq) / (1.f + sq);

        {   // agreement -> logits (initial logits 0, plain store)
            float r[8];
#pragma unroll
            for (int q = 0; q < 8; ++q) r[q] = vq[q] * act;
#pragma unroll
            for (int st = 8; st; st >>= 1)
#pragma unroll
                for (int q = 0; q < 8; ++q)
                    r[q] += __shfl_xor_sync(0xffffffffu, r[q], st, 16);
            if (d < 8) {
                float val = r[0];
#pragma unroll
                for (int q = 1; q < 8; ++q) if (d == q) val = r[q];
                lg[d * 16 + o] = val;
            }
        }
        __syncthreads();

#pragma unroll
        for (int it = 1; it < 3; ++it) {
            if (t < 128) {          // softmax over o, per input capsule
                float l = lg[t];
                float mx = l;
#pragma unroll
                for (int st = 8; st; st >>= 1)
                    mx = fmaxf(mx, __shfl_xor_sync(0xffffffffu, mx, st, 16));
                float e = __expf(l - mx);
                float sum = e;
#pragma unroll
                for (int st = 8; st; st >>= 1)
                    sum += __shfl_xor_sync(0xffffffffu, sum, st, 16);
                rt[t] = e / sum;
            }
            __syncthreads();

            pre = bval;
#pragma unroll
            for (int q = 0; q < 8; ++q)
                pre = fmaf(rt[q * 16 + o], vq[q], pre);
            sq = pre * pre;
#pragma unroll
            for (int st = 8; st; st >>= 1)
                sq += __shfl_xor_sync(0xffffffffu, sq, st, 16);
            act = pre * sqrtf(sq) / (1.f + sq);

            if (it == 1) {
                float r[8];
#pragma unroll
                for (int q = 0; q < 8; ++q) r[q] = vq[q] * act;
#pragma unroll
                for (int st = 8; st; st >>= 1)
#pragma unroll
                    for (int q = 0; q < 8; ++q)
                        r[q] += __shfl_xor_sync(0xffffffffu, r[q], st, 16);
                if (d < 8) {
                    float val = r[0];
#pragma unroll
                    for (int q = 1; q < 8; ++q) if (d == q) val = r[q];
                    lg[d * 16 + o] += val;
                }
                __syncthreads();
            }
        }

        out[(((size_t)p * 32 + h) * 32 + (w0 + pt)) * 256 + t] = act;
        __syncthreads();
    }
}

extern "C" void kernel_launch(void* const* d_in, const int* in_sizes, int n_in,
                              void* d_out, int out_size) {
    const float* x  = (const float*)d_in[0];
    const float* Wt = (const float*)d_in[1];
    const float* b  = (const float*)d_in[2];
    float* out = (float*)d_out;

    cudaFuncSetAttribute(caps_fused_kernel,
                         cudaFuncAttributeMaxDynamicSharedMemorySize, SMEM_ALLOC);

    xprep_kernel<<<2048, 256>>>(x);
    wprep_kernel<<<26, 256>>>(Wt);
    caps_fused_kernel<<<2048, 256, SMEM_ALLOC>>>(b, out);
}

// round 12
// speedup vs baseline: 2.0023x; 1.4838x over previous
#include <cuda_runtime.h>
#include <cuda_fp16.h>
#include <cstdint>
#include <cstddef>

// ---------------------------------------------------------------------------
//  x: [16, 32, 32, 8, 16]  (B,H,W,I,Din) fp32
//  W: [5, 5, 16, 256]      (kh,kw,cin,co) fp32, co = o*16+d
//  b: [1, 1, 16, 16]       fp32
//  out: [16, 32, 32, 16, 16] (B,H,W,O,D) fp32
//
// Routing group p uses conv images n = 8p+q -> input capsule i = p>>1,
// b_img = 8*(p&1)+q.  CTA = (p, h, 8 w's): M=64 GEMM rows (8 q x 8 w) =
// the votes its 8 routing points need.  2048 CTAs, 256 threads, occupancy 2.
// GEMM: M=64, N=256, K=416 (26 taps x 16, tap 25 zero-padded).
// Single-pass fp16 (x,W fp16): measured rel_err 5.7e-4 < 1e-3.
// 13 super-steps of 2 taps (32 HMMA/warp/step), 3-stage cp.async.
// Warp-parallel routing epilogue (one warp per point, shuffle-only).
// R11 fix: dump row stride 258 -> 260 floats (1040B, 16B-aligned rows) so the
// epilogue's float4 reads are aligned (258*4 = 1032 was 8-mod-16 on odd rows).
// ---------------------------------------------------------------------------

__device__ __half g_xh[16 * 32 * 32 * 8 * 16];   // x as fp16
__device__ __half g_ws[26 * 256 * 16];           // W as [k][n][16k], fp16, tap25=0

// stage: A 2 taps x 64x48B (6144) + B 2 taps x 256x48B (24576) = 30720
#define ST_BYTES   30720
#define SMEM_ALLOC 92160           // 3 stages; dump buffer (66.6KB) reuses stages
#define DPITCH     260             // dump row pitch in floats (1040B, 16-aligned)

__device__ __forceinline__ uint32_t smem_u32(const void* p) {
    uint32_t a;
    asm("{ .reg .u64 t; cvta.to.shared.u64 t, %1; cvt.u32.u64 %0, t; }" : "=r"(a) : "l"(p));
    return a;
}
__device__ __forceinline__ void cp16z(uint32_t dst, const void* src, bool valid) {
    int sz = valid ? 16 : 0;
    asm volatile("cp.async.cg.shared.global [%0], [%1], 16, %2;\n"
                 :: "r"(dst), "l"(src), "r"(sz));
}
__device__ __forceinline__ void cp16(uint32_t dst, const void* src) {
    asm volatile("cp.async.cg.shared.global [%0], [%1], 16;\n" :: "r"(dst), "l"(src));
}
#define CP_COMMIT() asm volatile("cp.async.commit_group;\n")
#define CP_WAIT(n)  asm volatile("cp.async.wait_group %0;\n" :: "n"(n))

#define LDSM4(r, addr) \
    asm volatile("ldmatrix.sync.aligned.m8n8.x4.shared.b16 {%0,%1,%2,%3}, [%4];" \
                 : "=r"((r)[0]), "=r"((r)[1]), "=r"((r)[2]), "=r"((r)[3]) : "r"(addr))

#define MMA16816(c, a, bb0, bb1) \
    asm volatile("mma.sync.aligned.m16n8k16.row.col.f32.f16.f16.f32 " \
                 "{%0,%1,%2,%3}, {%4,%5,%6,%7}, {%8,%9}, {%0,%1,%2,%3};" \
                 : "+f"((c)[0]), "+f"((c)[1]), "+f"((c)[2]), "+f"((c)[3]) \
                 : "r"((a)[0]), "r"((a)[1]), "r"((a)[2]), "r"((a)[3]), \
                   "r"(bb0), "r"(bb1))

// ---------------- prep kernels ----------------
__global__ void xprep_kernel(const float* __restrict__ x) {
    int idx = blockIdx.x * 256 + threadIdx.x;          // 4 floats per thread
    if (idx >= 16 * 32 * 32 * 8 * 16 / 4) return;
    float4 f = ((const float4*)x)[idx];
    __half h0[4];
    h0[0] = __float2half_rn(f.x);
    h0[1] = __float2half_rn(f.y);
    h0[2] = __float2half_rn(f.z);
    h0[3] = __float2half_rn(f.w);
    *(uint2*)&g_xh[idx * 4] = *(uint2*)h0;
}

__global__ void wprep_kernel(const float* __restrict__ W) {
    int idx = blockIdx.x * 256 + threadIdx.x;   // k*256 + co, k in [0,26)
    if (idx >= 26 * 256) return;
    int co = idx & 255, k = idx >> 8;
#pragma unroll
    for (int cin = 0; cin < 16; ++cin)
        g_ws[idx * 16 + cin] = (k < 25)
            ? __float2half_rn(W[(k * 16 + cin) * 256 + co])
            : __half(0.f);
}

// ---------------- main fused kernel ----------------
// Load one super-stage = taps 2s, 2s+1.
__device__ __forceinline__ void load_tiles(uint32_t sbase, int s, int stg_i,
                                           int h, int w0, int i_true, int b_base,
                                           int t) {
    const uint32_t stg = sbase + stg_i * ST_BYTES;
    // A: 256 x 16B (1 per thread): sub(2) x half(2) x row(64)
    {
        int sub = t >> 7, r = t & 127;
        int half = r & 1, row = r >> 1;
        int k2 = 2 * s + sub;
        int kh = k2 / 5, kw = k2 - kh * 5;
        int q = row >> 3, wl = row & 7;
        int hh = h + kh - 2, ww = w0 + wl + kw - 2;
        bool valid = (k2 < 25) && ((unsigned)hh < 32u) && ((unsigned)ww < 32u);
        const __half* src = valid
            ? &g_xh[((((size_t)(b_base + q) * 32 + hh) * 32 + ww) * 8 + i_true) * 16 + half * 8]
            : &g_xh[0];
        cp16z(stg + sub * 3072 + row * 48 + half * 16, src, valid);
    }
    // B: 1024 x 16B (4 per thread): sub(2) x half(2) x n(256)
#pragma unroll
    for (int it = 0; it < 4; ++it) {
        int j = t + it * 256;
        int sub = j >> 9, rem = j & 511;
        int half = rem & 1, n = rem >> 1;
        cp16(stg + 6144 + sub * 12288 + n * 48 + half * 16,
             &g_ws[((size_t)(2 * s + sub) * 256 + n) * 16 + half * 8]);
    }
}

__global__ __launch_bounds__(256, 2) void caps_fused_kernel(
    const float* __restrict__ bias, float* __restrict__ out) {
    extern __shared__ __align__(1024) char sm[];
    const uint32_t sbase = smem_u32(sm);

    const int t = threadIdx.x;
    const int wid = t >> 5, lane = t & 31;
    const int bid = blockIdx.x;
    const int wblk = bid & 3, h = (bid >> 2) & 31, p = bid >> 7;
    const int w0 = wblk * 8;
    const int i_true = p >> 1, b_base = (p & 1) * 8;

    const int wm = wid & 1;        // m block (32 rows each)
    const int wn = wid >> 1;       // n block (64 cols each)

    const uint32_t a_row  = lane & 15;
    const uint32_t a_koff = (lane >> 4) * 16;
    const uint32_t b_row  = (lane & 7) + ((lane >> 4) << 3);
    const uint32_t b_koff = ((lane >> 3) & 1) * 16;

    float acc[2][8][4];
#pragma unroll
    for (int mi = 0; mi < 2; ++mi)
#pragma unroll
        for (int ni = 0; ni < 8; ++ni)
#pragma unroll
            for (int j = 0; j < 4; ++j) acc[mi][ni][j] = 0.f;

    // prologue: stages 0,1
    load_tiles(sbase, 0, 0, h, w0, i_true, b_base, t);
    CP_COMMIT();
    load_tiles(sbase, 1, 1, h, w0, i_true, b_base, t);
    CP_COMMIT();

    for (int s = 0; s < 13; ++s) {
        const int stg_i = s % 3;
        if (s < 12) CP_WAIT(1); else CP_WAIT(0);
        __syncthreads();                 // stage s ready; stage (s+2)%3 free
        if (s + 2 < 13) {
            load_tiles(sbase, s + 2, (s + 2) % 3, h, w0, i_true, b_base, t);
            CP_COMMIT();
        }

        const uint32_t stg = sbase + stg_i * ST_BYTES;
#pragma unroll
        for (int sub = 0; sub < 2; ++sub) {
            const uint32_t Ab = stg + sub * 3072 + (wm * 32 + a_row) * 48 + a_koff;
            const uint32_t Bb = stg + 6144 + sub * 12288 +
                                (wn * 64 + b_row) * 48 + b_koff;
            uint32_t Af[2][4], Bf[4][4];
#pragma unroll
            for (int mi = 0; mi < 2; ++mi) LDSM4(Af[mi], Ab + mi * 768);
#pragma unroll
            for (int nt = 0; nt < 4; ++nt) LDSM4(Bf[nt], Bb + nt * 768);
#pragma unroll
            for (int mi = 0; mi < 2; ++mi)
#pragma unroll
                for (int nt = 0; nt < 4; ++nt) {
                    MMA16816(acc[mi][2 * nt],     Af[mi], Bf[nt][0], Bf[nt][1]);
                    MMA16816(acc[mi][2 * nt + 1], Af[mi], Bf[nt][2], Bf[nt][3]);
                }
        }
    }
    __syncthreads();   // compute done; stage smem dead -> vote dump

    // ---- dump accumulators: Dsm[row 64][col 256], pitch DPITCH floats ----
    float* Dsm = (float*)sm;
    {
        const int g = lane >> 2, tq = lane & 3;
#pragma unroll
        for (int mi = 0; mi < 2; ++mi)
#pragma unroll
            for (int ni = 0; ni < 8; ++ni) {
                int row = wm * 32 + mi * 16 + g;
                int col = wn * 64 + ni * 8 + tq * 2;
                *(float2*)&Dsm[(size_t)row * DPITCH + col] =
                    make_float2(acc[mi][ni][0], acc[mi][ni][1]);
                *(float2*)&Dsm[(size_t)(row + 8) * DPITCH + col] =
                    make_float2(acc[mi][ni][2], acc[mi][ni][3]);
            }
    }
    __syncthreads();

    // ---- warp-parallel routing: warp wid handles point pt = wid ----
    // lane l: o = l>>1, d-group dg = l&1 (d = dg*8 + j).  All reductions are
    // warp shuffles: squash-norm over d via xor 1; softmax over o via
    // butterfly strides {2,4,8,16}.  No block barriers.
    {
        const int o = lane >> 1, dg = lane & 1;

        // votes: vqv[q][j] = Dsm[(q*8+wid)][o*16 + dg*8 + j]
        float vqv[8][8];
#pragma unroll
        for (int q = 0; q < 8; ++q) {
            const float* rowp = &Dsm[(size_t)(q * 8 + wid) * DPITCH + lane * 8];
            float4 v0 = *(const float4*)rowp;
            float4 v1 = *(const float4*)(rowp + 4);
            vqv[q][0] = v0.x; vqv[q][1] = v0.y; vqv[q][2] = v0.z; vqv[q][3] = v0.w;
            vqv[q][4] = v1.x; vqv[q][5] = v1.y; vqv[q][6] = v1.z; vqv[q][7] = v1.w;
        }
        float bv[8];
        {
            const float4* bp = (const float4*)(bias + o * 16 + dg * 8);
            float4 b0 = bp[0], b1 = bp[1];
            bv[0] = b0.x; bv[1] = b0.y; bv[2] = b0.z; bv[3] = b0.w;
            bv[4] = b1.x; bv[5] = b1.y; bv[6] = b1.z; bv[7] = b1.w;
        }

        float pre[8], act[8], lgv[8];

        // ---- iter 0: route = 1/16 ----
#pragma unroll
        for (int j = 0; j < 8; ++j) {
            float s = bv[j];
#pragma unroll
            for (int q = 0; q < 8; ++q) s = fmaf(0.0625f, vqv[q][j], s);
            pre[j] = s;
        }
        float sq = 0.f;
#pragma unroll
        for (int j = 0; j < 8; ++j) sq = fmaf(pre[j], pre[j], sq);
        sq += __shfl_xor_sync(0xffffffffu, sq, 1);
        float scl = sqrtf(sq) / (1.f + sq);
#pragma unroll
        for (int j = 0; j < 8; ++j) act[j] = pre[j] * scl;

        // agreement -> logits
#pragma unroll
        for (int q = 0; q < 8; ++q) {
            float s = 0.f;
#pragma unroll
            for (int j = 0; j < 8; ++j) s = fmaf(vqv[q][j], act[j], s);
            lgv[q] = s + __shfl_xor_sync(0xffffffffu, s, 1);
        }

#pragma unroll
        for (int it = 1; it < 3; ++it) {
            // softmax over o (lane pairs share o; butterfly over strides 2..16)
            float mx[8], ex[8], sum[8];
#pragma unroll
            for (int q = 0; q < 8; ++q) mx[q] = lgv[q];
#pragma unroll
            for (int st = 2; st <= 16; st <<= 1)
#pragma unroll
                for (int q = 0; q < 8; ++q)
                    mx[q] = fmaxf(mx[q], __shfl_xor_sync(0xffffffffu, mx[q], st));
#pragma unroll
            for (int q = 0; q < 8; ++q) { ex[q] = __expf(lgv[q] - mx[q]); sum[q] = ex[q]; }
#pragma unroll
            for (int st = 2; st <= 16; st <<= 1)
#pragma unroll
                for (int q = 0; q < 8; ++q)
                    sum[q] += __shfl_xor_sync(0xffffffffu, sum[q], st);
            float route[8];
#pragma unroll
            for (int q = 0; q < 8; ++q) route[q] = ex[q] / sum[q];

#pragma unroll
            for (int j = 0; j < 8; ++j) {
                float s = bv[j];
#pragma unroll
                for (int q = 0; q < 8; ++q) s = fmaf(route[q], vqv[q][j], s);
                pre[j] = s;
            }
            sq = 0.f;
#pragma unroll
            for (int j = 0; j < 8; ++j) sq = fmaf(pre[j], pre[j], sq);
            sq += __shfl_xor_sync(0xffffffffu, sq, 1);
            scl = sqrtf(sq) / (1.f + sq);
#pragma unroll
            for (int j = 0; j < 8; ++j) act[j] = pre[j] * scl;

            if (it == 1) {
#pragma unroll
                for (int q = 0; q < 8; ++q) {
                    float s = 0.f;
#pragma unroll
                    for (int j = 0; j < 8; ++j) s = fmaf(vqv[q][j], act[j], s);
                    lgv[q] += s + __shfl_xor_sync(0xffffffffu, s, 1);
                }
            }
        }

        // write out: point (p, h, w0+wid), lane covers cols lane*8..lane*8+7
        float* op = out + (((size_t)p * 32 + h) * 32 + (w0 + wid)) * 256 + lane * 8;
        *(float4*)op       = make_float4(act[0], act[1], act[2], act[3]);
        *(float4*)(op + 4) = make_float4(act[4], act[5], act[6], act[7]);
    }
}

extern "C" void kernel_launch(void* const* d_in, const int* in_sizes, int n_in,
                              void* d_out, int out_size) {
    const float* x  = (const float*)d_in[0];
    const float* Wt = (const float*)d_in[1];
    const float* b  = (const float*)d_in[2];
    float* out = (float*)d_out;

    cudaFuncSetAttribute(caps_fused_kernel,
                         cudaFuncAttributeMaxDynamicSharedMemorySize, SMEM_ALLOC);

    xprep_kernel<<<2048, 256>>>(x);
    wprep_kernel<<<26, 256>>>(Wt);
    caps_fused_kernel<<<2048, 256, SMEM_ALLOC>>>(b, out);
}